// round 3
// baseline (speedup 1.0000x reference)
#include <cuda_runtime.h>
#include <cstdint>

// EdgeFeature: B=4, D=64, N=4096, K=16
// out = [ edge_feature (4,128,4096,16) fp32 ; idx (4,65536) as fp32 ]

#define B_ 4
#define D_ 64
#define N_ 4096
#define K_ 16

// Scratch (static __device__ — no allocations allowed in kernel_launch)
__device__ float g_sq[B_ * N_];                       // 64 KB
__device__ float g_dist[(size_t)B_ * N_ * N_];        // 256 MB (fp32 dist, post-sqrt)
__device__ int   g_idx[B_ * N_ * K_];                 // 1 MB

// packed f32x2 FMA (Blackwell): both lanes are independent IEEE fp32 FMAs,
// so results are bitwise identical to scalar fmaf chains.
__device__ __forceinline__ void fma2(unsigned long long& c,
                                     unsigned long long a, unsigned long long b) {
    asm("fma.rn.f32x2 %0, %1, %2, %0;" : "+l"(c) : "l"(a), "l"(b));
}
__device__ __forceinline__ float2 unpk(unsigned long long p) {
    float2 r;
    r.x = __uint_as_float((unsigned)p);
    r.y = __uint_as_float((unsigned)(p >> 32));
    return r;
}

// ---------------------------------------------------------------------------
// 1) squared norms (sequential ascending d, fmaf — matches the GEMM's dot
//    accumulation order so self-distance cancels to exactly 0.0f)
// ---------------------------------------------------------------------------
__global__ void sq_kernel(const float* __restrict__ pc) {
    int gid = blockIdx.x * blockDim.x + threadIdx.x;
    int b = gid >> 12;
    int n = gid & (N_ - 1);
    const float* X = pc + (size_t)b * D_ * N_;
    float acc = 0.0f;
    #pragma unroll
    for (int d = 0; d < D_; d++) {
        float v = X[d * N_ + n];
        acc = fmaf(v, v, acc);
    }
    g_sq[gid] = acc;
}

// ---------------------------------------------------------------------------
// 2) dist = sqrt(max(sq_i + sq_j - 2*dot, 0)) — upper-triangle tiles only.
//    dist(i,j) is bitwise == dist(j,i) (identical FMA chains), so off-diagonal
//    tiles are stored twice (normal + transposed). FFMA2 mainloop: A-tile is
//    stored DUPLICATED in smem so {a,a} pairs come straight from LDS.
// ---------------------------------------------------------------------------
__global__ __launch_bounds__(256, 2) void d2_kernel(const float* __restrict__ pc) {
    __shared__ float As2[16][256];   // duplicated: As2[d][2i]=As2[d][2i+1]=A[d][i]
    __shared__ float Bs[16][128];
    __shared__ float sqa[128];
    __shared__ float sqb[128];

    int b = blockIdx.z;
    // decode linear tile id -> (by, bx) with bx >= by  (528 tiles)
    int tl = blockIdx.x;
    int by = 0;
    #pragma unroll 1
    while (tl >= 32 - by) { tl -= 32 - by; by++; }
    int bx = by + tl;

    int i0 = by * 128;
    int j0 = bx * 128;
    const float* X = pc + (size_t)b * D_ * N_;
    int t = threadIdx.x;

    if (t < 128) sqa[t]       = g_sq[b * N_ + i0 + t];
    else         sqb[t - 128] = g_sq[b * N_ + j0 + (t - 128)];

    int r = t >> 4;    // 0..15 row group (rows i0 + r*8 .. +7)
    int c = t & 15;    // 0..15 col group (cols j0 + c*8 .. +7)

    unsigned long long acc2[8][4];   // [ii][jj2]: pair of adjacent columns
    #pragma unroll
    for (int ii = 0; ii < 8; ii++)
        #pragma unroll
        for (int q = 0; q < 4; q++) acc2[ii][q] = 0ull;

    for (int dc = 0; dc < D_; dc += 16) {
        __syncthreads();
        // load 16x128 tiles: A duplicated into As2, B normal
        #pragma unroll
        for (int l0 = 0; l0 < 512; l0 += 256) {
            int l  = l0 + t;
            int d  = l >> 5;
            int i4 = (l & 31) << 2;
            float4 va = *(const float4*)&X[(size_t)(dc + d) * N_ + i0 + i4];
            float4 vb = *(const float4*)&X[(size_t)(dc + d) * N_ + j0 + i4];
            float4 w0 = make_float4(va.x, va.x, va.y, va.y);
            float4 w1 = make_float4(va.z, va.z, va.w, va.w);
            *(float4*)&As2[d][i4 * 2]     = w0;
            *(float4*)&As2[d][i4 * 2 + 4] = w1;
            *(float4*)&Bs[d][i4]          = vb;
        }
        __syncthreads();

        #pragma unroll
        for (int d = 0; d < 16; d++) {
            // 8 {a,a} dup-pairs for this thread's rows (pre-duplicated in smem)
            ulonglong2 A0 = *(const ulonglong2*)&As2[d][r * 16];
            ulonglong2 A1 = *(const ulonglong2*)&As2[d][r * 16 + 4];
            ulonglong2 A2 = *(const ulonglong2*)&As2[d][r * 16 + 8];
            ulonglong2 A3 = *(const ulonglong2*)&As2[d][r * 16 + 12];
            // 4 natural {b0,b1} pairs for this thread's cols
            ulonglong2 B0 = *(const ulonglong2*)&Bs[d][c * 8];
            ulonglong2 B1 = *(const ulonglong2*)&Bs[d][c * 8 + 4];
            unsigned long long ad[8] = {A0.x, A0.y, A1.x, A1.y, A2.x, A2.y, A3.x, A3.y};
            unsigned long long bp[4] = {B0.x, B0.y, B1.x, B1.y};
            #pragma unroll
            for (int ii = 0; ii < 8; ii++)
                #pragma unroll
                for (int q = 0; q < 4; q++)
                    fma2(acc2[ii][q], ad[ii], bp[q]);
        }
    }

    // epilogue: dist values (2*acc exact -> rounding matches reference)
    float v[8][8];
    #pragma unroll
    for (int ii = 0; ii < 8; ii++) {
        float si = sqa[r * 8 + ii];
        #pragma unroll
        for (int q = 0; q < 4; q++) {
            float2 d2 = unpk(acc2[ii][q]);
            float s0 = si + sqb[c * 8 + 2 * q];
            float s1 = si + sqb[c * 8 + 2 * q + 1];
            v[ii][2 * q]     = sqrtf(fmaxf(s0 - 2.0f * d2.x, 0.0f));
            v[ii][2 * q + 1] = sqrtf(fmaxf(s1 - 2.0f * d2.y, 0.0f));
        }
    }

    // normal store: rows i0+r*8+ii, cols j0+c*8..
    #pragma unroll
    for (int ii = 0; ii < 8; ii++) {
        float* dst = g_dist + ((size_t)(b * N_ + i0 + r * 8 + ii) << 12) + j0 + c * 8;
        *(float4*)&dst[0] = *(float4*)&v[ii][0];
        *(float4*)&dst[4] = *(float4*)&v[ii][4];
    }
    // transposed store for off-diagonal tiles: rows j0+c*8+jj, cols i0+r*8..
    if (bx != by) {
        #pragma unroll
        for (int jj = 0; jj < 8; jj++) {
            float* dst = g_dist + ((size_t)(b * N_ + j0 + c * 8 + jj) << 12) + i0 + r * 8;
            float4 w0 = make_float4(v[0][jj], v[1][jj], v[2][jj], v[3][jj]);
            float4 w1 = make_float4(v[4][jj], v[5][jj], v[6][jj], v[7][jj]);
            *(float4*)&dst[0] = w0;
            *(float4*)&dst[4] = w1;
        }
    }
}

// ---------------------------------------------------------------------------
// 3) per-row top-(K+1) via histogram threshold + tiny exact selection.
//    Bucket = dist_bits >> 21 (monotone for nonneg floats). Find the bucket
//    containing the 17th smallest, compact all candidates with bucket <= B
//    (typically ~25, worst case 4096), then one warp runs exact 17-pass
//    argmin on u64 keys (dist_bits<<32)|j -> identical order to lax.top_k.
// ---------------------------------------------------------------------------
__global__ __launch_bounds__(256) void select_kernel(float* __restrict__ out_idx_f) {
    __shared__ int hist[2048];
    __shared__ unsigned long long buf[4096];
    __shared__ int wsum[8];
    __shared__ int Bsh;
    __shared__ int cnt;

    int row = blockIdx.x;                      // b*4096 + i
    const float* src = g_dist + (size_t)row * N_;
    int t = threadIdx.x;
    int lane = t & 31, w = t >> 5;

    #pragma unroll
    for (int q = 0; q < 8; q++) hist[t + 256 * q] = 0;
    if (t == 0) cnt = 0;
    __syncthreads();

    unsigned bits[16];
    #pragma unroll
    for (int jj = 0; jj < 16; jj++) {
        bits[jj] = __float_as_uint(src[t + jj * 256]);
        atomicAdd(&hist[bits[jj] >> 21], 1);
    }
    __syncthreads();

    // scan over 2048 buckets: thread t owns buckets [t*8, t*8+8)
    int h[8], s = 0;
    #pragma unroll
    for (int q = 0; q < 8; q++) { h[q] = hist[t * 8 + q]; s += h[q]; }
    int x = s;
    #pragma unroll
    for (int off = 1; off < 32; off <<= 1) {
        int y = __shfl_up_sync(0xffffffffu, x, off);
        if (lane >= off) x += y;
    }
    if (lane == 31) wsum[w] = x;
    __syncthreads();
    int wo = 0;
    #pragma unroll
    for (int q = 0; q < 8; q++) wo += (q < w) ? wsum[q] : 0;
    int cum = wo + x - s;                      // exclusive prefix at chunk start
    #pragma unroll
    for (int q = 0; q < 8; q++) {
        if (cum < (K_ + 1) && cum + h[q] >= (K_ + 1)) Bsh = t * 8 + q;
        cum += h[q];
    }
    __syncthreads();

    int Bv = Bsh;
    #pragma unroll
    for (int jj = 0; jj < 16; jj++) {
        if ((int)(bits[jj] >> 21) <= Bv) {
            int p = atomicAdd(&cnt, 1);
            buf[p] = ((unsigned long long)bits[jj] << 32) | (unsigned)(t + jj * 256);
        }
    }
    __syncthreads();

    if (w == 0) {
        int n = cnt;
        for (int p = 0; p <= K_; p++) {
            unsigned long long m = 0xFFFFFFFFFFFFFFFFull;
            for (int i = lane; i < n; i += 32) m = (buf[i] < m) ? buf[i] : m;
            #pragma unroll
            for (int off = 16; off; off >>= 1) {
                unsigned long long o = __shfl_xor_sync(0xffffffffu, m, off);
                m = (o < m) ? o : m;
            }
            for (int i = lane; i < n; i += 32)
                if (buf[i] == m) buf[i] = 0xFFFFFFFFFFFFFFFFull;
            if (lane == 0 && p > 0) {
                int j = (int)(m & 0xFFFFFFFFu);
                g_idx[row * K_ + (p - 1)]     = j;
                out_idx_f[row * K_ + (p - 1)] = (float)j;
            }
        }
    }
}

// ---------------------------------------------------------------------------
// 4) gather + concat epilogue (unchanged: 69us, coalesced 1 KB stores)
// ---------------------------------------------------------------------------
__global__ __launch_bounds__(256) void gather_kernel(const float* __restrict__ pc,
                                                     float* __restrict__ out) {
    __shared__ int   sidx[32 * K_];
    __shared__ float cen[D_][32];

    int blk = blockIdx.x;             // 512 blocks
    int b   = blk >> 7;
    int n0  = (blk & 127) * 32;
    int t   = threadIdx.x;
    const float* pcb = pc + (size_t)b * D_ * N_;

    for (int l = t; l < 32 * K_; l += 256)
        sidx[l] = g_idx[(b * N_ + n0) * K_ + l];
    for (int l = t; l < D_ * 32; l += 256) {
        int d = l >> 5, n = l & 31;
        cen[d][n] = pcb[d * N_ + n0 + n];
    }
    __syncthreads();

    size_t obase = (size_t)b * 2 * D_ * N_ * K_;
    #pragma unroll 4
    for (int cch = 0; cch < D_; cch++) {
        #pragma unroll
        for (int q = 0; q < 2; q++) {
            int l = t + q * 256;
            int n = l >> 4, k = l & 15;
            float ce = cen[cch][n];
            float nb = __ldg(&pcb[cch * N_ + sidx[l]]);
            size_t o = obase + ((size_t)cch * N_ + n0 + n) * K_ + k;
            out[o]                        = ce;
            out[o + (size_t)D_ * N_ * K_] = nb - ce;
        }
    }
}

// ---------------------------------------------------------------------------
extern "C" void kernel_launch(void* const* d_in, const int* in_sizes, int n_in,
                              void* d_out, int out_size) {
    const float* pc = (const float*)d_in[0];
    float* out = (float*)d_out;
    float* out_idx = out + (size_t)B_ * 2 * D_ * N_ * K_;

    sq_kernel<<<(B_ * N_) / 256, 256>>>(pc);
    dim3 gg(528, 1, B_);                      // upper-triangle tiles
    d2_kernel<<<gg, 256>>>(pc);
    select_kernel<<<B_ * N_, 256>>>(out_idx);
    gather_kernel<<<(B_ * N_) / 32, 256>>>(pc, out);
}